// round 4
// baseline (speedup 1.0000x reference)
#include <cuda_runtime.h>

// BEVFeatureExtractorV2 — R4: spatially-sorted point schedule for L2 reuse.
// feats: (B=4, C=256, H=256, W=256) fp32   rois: (B=4, N=512, 7) fp32
// out: (B, N, 5*C) fp32
//
// Pipeline: [zero counts] -> [params + bucket key + rank] -> [prefix sum]
//           -> [scatter order] -> [main gather in bucket order]
// Bucket key = (batch<<8)|y0 : points hitting the same rows run concurrently,
// so overlapping 64B DRAM atoms dedup in L2 instead of refetching.

#define BB 4
#define NN 512
#define CC 256
#define HH 256
#define WW 256
#define NPTS 5
#define HWSZ (HH * WW)
#define NPOINTS (BB * NN * NPTS)   // 10240
#define NBUCK (BB * HH)            // 1024

__device__ float4 g_w[NPOINTS];          // wa, wb, wc, wd
__device__ int4   g_a[NPOINTS];          // r0, r1, packed(off0|off1<<8|b<<16), o01
__device__ int    g_key[NPOINTS];
__device__ int    g_rank[NPOINTS];
__device__ int    g_order[NPOINTS];
__device__ int    g_cnt[NBUCK];
__device__ int    g_base[NBUCK];

__global__ void k_zero()
{
    int i = blockIdx.x * blockDim.x + threadIdx.x;
    if (i < NBUCK) g_cnt[i] = 0;
}

__global__ void k_params(const float* __restrict__ rois)
{
    const int i = blockIdx.x * blockDim.x + threadIdx.x;
    if (i >= NPOINTS) return;

    const int p = i % NPTS;
    const int n = (i / NPTS) % NN;
    const int b = i / (NPTS * NN);

    const float* roi = rois + (b * NN + n) * 7;
    const float cx = roi[0];
    const float cy = roi[1];
    const float dx = roi[3];
    const float dy = roi[4];
    const float ry = roi[6];

    float sn, cs;
    sincosf(ry, &sn, &cs);

    // rot(x, y) = (x*cos + y*sin, -x*sin + y*cos)  (row-vector * R)
    float px = cx, py = cy;
    const float hx = 0.5f * dx, hy = 0.5f * dy;
    if (p == 1)      { px = cx - hx * cs; py = cy + hx * sn; }
    else if (p == 2) { px = cx + hx * cs; py = cy - hx * sn; }
    else if (p == 3) { px = cx - hy * sn; py = cy - hy * cs; }
    else if (p == 4) { px = cx + hy * sn; py = cy + hy * cs; }

    const float x = (px + 51.2f) / 0.1f / 4.0f;
    const float y = (py + 51.2f) / 0.1f / 4.0f;

    const float xf = floorf(x);
    const float yf = floorf(y);
    int x0 = (int)xf,  x1 = (int)xf + 1;
    int y0 = (int)yf,  y1 = (int)yf + 1;
    x0 = min(max(x0, 0), WW - 1);
    x1 = min(max(x1, 0), WW - 1);
    y0 = min(max(y0, 0), HH - 1);
    y1 = min(max(y1, 0), HH - 1);

    const float x0f = (float)x0, x1f = (float)x1;
    const float y0f = (float)y0, y1f = (float)y1;
    float4 w;
    w.x = (x1f - x) * (y1f - y);   // (y0, x0)
    w.y = (x1f - x) * (y - y0f);   // (y1, x0)
    w.z = (x - x0f) * (y1f - y);   // (y0, x1)
    w.w = (x - x0f) * (y - y0f);   // (y1, x1)
    g_w[i] = w;

    const int q    = x0 & ~3;
    const int off0 = x0 - q;          // 0..3
    const int off1 = x1 - q;          // >3 => x1 outside quad

    int4 a;
    a.x = y0 * WW + q;                // r0
    a.y = y1 * WW + q;                // r1
    a.z = off0 | (off1 << 8) | (b << 16);
    a.w = y0 * WW + x1;               // o01  (o11 = o01 + (r1 - r0))
    g_a[i] = a;

    const int key = (b << 8) | y0;
    g_key[i]  = key;
    g_rank[i] = atomicAdd(&g_cnt[key], 1);
}

__global__ void k_prefix()
{
    __shared__ int s[NBUCK];
    const int t = threadIdx.x;          // blockDim.x == NBUCK
    int v = g_cnt[t];
    s[t] = v;
    __syncthreads();
    // Hillis-Steele inclusive scan
    for (int d = 1; d < NBUCK; d <<= 1) {
        int add = (t >= d) ? s[t - d] : 0;
        __syncthreads();
        s[t] += add;
        __syncthreads();
    }
    g_base[t] = s[t] - v;               // exclusive
}

__global__ void k_scatter()
{
    const int i = blockIdx.x * blockDim.x + threadIdx.x;
    if (i >= NPOINTS) return;
    g_order[g_base[g_key[i]] + g_rank[i]] = i;
}

__device__ __forceinline__ float f4_get(const float4& v, int i) {
    return (i == 0) ? v.x : (i == 1) ? v.y : (i == 2) ? v.z : v.w;
}

__global__ __launch_bounds__(64, 28) void bev_extract_kernel(
    const float* __restrict__ feats,
    float* __restrict__ out)
{
    const int gwarp = (blockIdx.x * blockDim.x + threadIdx.x) >> 5;
    const int lane  = threadIdx.x & 31;
    if (gwarp >= NPOINTS) return;

    const int j = g_order[gwarp];        // spatially-sorted point id

    const float4 w = g_w[j];
    const int4   a = g_a[j];
    const int r0   = a.x;
    const int r1   = a.y;
    const int off0 = a.z & 0xff;
    const int off1 = (a.z >> 8) & 0xff;
    const int b    = a.z >> 16;
    const int o01  = a.w;
    const int o11  = o01 + (r1 - r0);
    const bool in_quad = (off1 <= 3);    // warp-uniform

    const float* __restrict__ base = feats + (size_t)b * CC * HWSZ;
    float* __restrict__ outp = out + (size_t)j * CC;   // j == ((b*NN+n)*NPTS+p)

    if (in_quad) {
        #pragma unroll
        for (int k = 0; k < CC / 32; k++) {
            const int c = lane + 32 * k;
            const float* __restrict__ f = base + c * HWSZ;
            const float4 v0 = __ldg((const float4*)(f + r0));
            const float4 v1 = __ldg((const float4*)(f + r1));
            const float ia = f4_get(v0, off0);
            const float ic = f4_get(v0, off1);
            const float ib = f4_get(v1, off0);
            const float id = f4_get(v1, off1);
            outp[c] = w.x * ia + w.y * ib + w.z * ic + w.w * id;
        }
    } else {
        // off0 == 3, x1 in next quad: scalar taps for x1.
        #pragma unroll
        for (int k = 0; k < CC / 32; k++) {
            const int c = lane + 32 * k;
            const float* __restrict__ f = base + c * HWSZ;
            const float4 v0 = __ldg((const float4*)(f + r0));
            const float4 v1 = __ldg((const float4*)(f + r1));
            const float ic = __ldg(f + o01);
            const float id = __ldg(f + o11);
            outp[c] = w.x * v0.w + w.y * v1.w + w.z * ic + w.w * id;
        }
    }
}

extern "C" void kernel_launch(void* const* d_in, const int* in_sizes, int n_in,
                              void* d_out, int out_size)
{
    const float* feats = (const float*)d_in[0];
    const float* rois  = (const float*)d_in[1];
    float* out = (float*)d_out;

    k_zero<<<(NBUCK + 255) / 256, 256>>>();
    k_params<<<(NPOINTS + 127) / 128, 128>>>(rois);
    k_prefix<<<1, NBUCK>>>();
    k_scatter<<<(NPOINTS + 127) / 128, 128>>>();

    const int threads = 64;                                  // 2 warps/block
    const int blocks = (NPOINTS * 32 + threads - 1) / threads;   // 5120
    bev_extract_kernel<<<blocks, threads>>>(feats, out);
}